// round 2
// baseline (speedup 1.0000x reference)
#include <cuda_runtime.h>
#include <stdint.h>

#define IN_F   4096
#define OUT_F  11008
#define BITS   4
#define GROUP  128

#define CHUNK   256                 // inputs handled per block (split-K chunk)
#define NCHUNK  (IN_F / CHUNK)      // 16
#define TILE_O  256                 // outputs per block
#define NTILE   (OUT_F / TILE_O)    // 43  (43*256 == 11008 exactly)
#define NTAB    (CHUNK / 8)         // 32 tables of 256 entries
#define GRP_PER_CHUNK (CHUNK / GROUP)   // 2
#define THREADS 256

__global__ void __launch_bounds__(THREADS) zero_out_kernel(float* __restrict__ out) {
    int i = blockIdx.x * THREADS + threadIdx.x;
    if (i < OUT_F) out[i] = 0.0f;
}

__global__ void __launch_bounds__(THREADS) lutgemm_kernel(
    const float*    __restrict__ x,
    const uint32_t* __restrict__ qweight,
    const float*    __restrict__ alpha,
    const float*    __restrict__ qbias,
    float*          __restrict__ out)
{
    __shared__ float lut[NTAB * 256];   // 32 KB: per-byte-group sign-sum tables
    __shared__ float xs[CHUNK];
    __shared__ float wsum[THREADS / 32];
    __shared__ float Sg[GRP_PER_CHUNK];

    const int t     = threadIdx.x;
    const int chunk = blockIdx.y;                  // which 256-input slice
    const int o     = blockIdx.x * TILE_O + t;     // this thread's output column

    // ---- stage x chunk + warp-level partial sums for group sums ----
    float myx = x[chunk * CHUNK + t];
    xs[t] = myx;
    {
        float v = myx;
        #pragma unroll
        for (int s = 16; s; s >>= 1) v += __shfl_down_sync(0xffffffffu, v, s);
        if ((t & 31) == 0) wsum[t >> 5] = v;
    }
    __syncthreads();

    // group sums (each group = 128 inputs = 4 warps' worth of x)
    if (t == 0) Sg[0] = wsum[0] + wsum[1] + wsum[2] + wsum[3];
    if (t == 1) Sg[1] = wsum[4] + wsum[5] + wsum[6] + wsum[7];

    // ---- build LUTs: 8 threads per table, 32 gray-code entries each ----
    // Table tb covers inputs [chunk*256 + tb*8, +8).
    // T[v] = sum_j (2*bit_j(v)-1) * x_j
    {
        const int tb    = t >> 3;
        const int start = (t & 7) * 32;
        const uint32_t g0 = (uint32_t)start ^ ((uint32_t)start >> 1);

        float v2[8];
        #pragma unroll
        for (int j = 0; j < 8; ++j) v2[j] = 2.0f * xs[tb * 8 + j];

        float acc = 0.0f;
        #pragma unroll
        for (int j = 0; j < 8; ++j)
            acc += ((g0 >> j) & 1u) ? 0.5f * v2[j] : -0.5f * v2[j];

        float* T = lut + tb * 256;
        T[g0] = acc;

        #pragma unroll
        for (int j = 1; j < 32; ++j) {
            const int k = (j & 1) ? 0 : (j & 2) ? 1 : (j & 4) ? 2 : (j & 8) ? 3 : 4;
            const uint32_t g = g0 ^ (uint32_t)(j ^ (j >> 1));   // gray(start+j)
            acc += ((g >> k) & 1u) ? v2[k] : -v2[k];
            T[g] = acc;
        }
    }
    __syncthreads();

    // ---- main lookup loop ----
    // qweight index (w, b, o) = (w*4 + b)*OUT_F + o
    // word w uses local tables (w_local*4 + bytepos), w_local = gl*4 + wl
    float y = 0.0f;
    const int g_base = chunk * GRP_PER_CHUNK;

    #pragma unroll
    for (int gl = 0; gl < GRP_PER_CHUNK; ++gl) {
        const int g = g_base + gl;
        float p0 = 0.f, p1 = 0.f, p2 = 0.f, p3 = 0.f;

        #pragma unroll
        for (int wl = 0; wl < 4; ++wl) {
            const int w = g * 4 + wl;
            const float* Tw = lut + (gl * 4 + wl) * (4 * 256);
            const int base = (w * BITS) * OUT_F + o;

            const uint32_t q0 = __ldg(qweight + base);
            const uint32_t q1 = __ldg(qweight + base + OUT_F);
            const uint32_t q2 = __ldg(qweight + base + 2 * OUT_F);
            const uint32_t q3 = __ldg(qweight + base + 3 * OUT_F);

            p0 += Tw[q0 & 255u] + Tw[256 + ((q0 >> 8) & 255u)]
                + Tw[512 + ((q0 >> 16) & 255u)] + Tw[768 + (q0 >> 24)];
            p1 += Tw[q1 & 255u] + Tw[256 + ((q1 >> 8) & 255u)]
                + Tw[512 + ((q1 >> 16) & 255u)] + Tw[768 + (q1 >> 24)];
            p2 += Tw[q2 & 255u] + Tw[256 + ((q2 >> 8) & 255u)]
                + Tw[512 + ((q2 >> 16) & 255u)] + Tw[768 + (q2 >> 24)];
            p3 += Tw[q3 & 255u] + Tw[256 + ((q3 >> 8) & 255u)]
                + Tw[512 + ((q3 >> 16) & 255u)] + Tw[768 + (q3 >> 24)];
        }

        const int ab = (g * BITS) * OUT_F + o;
        float yg = p0 * __ldg(alpha + ab)
                 + p1 * __ldg(alpha + ab + OUT_F)
                 + p2 * __ldg(alpha + ab + 2 * OUT_F)
                 + p3 * __ldg(alpha + ab + 3 * OUT_F);
        yg += Sg[gl] * __ldg(qbias + g * OUT_F + o);
        y += yg;
    }

    atomicAdd(out + o, y);
}

extern "C" void kernel_launch(void* const* d_in, const int* in_sizes, int n_in,
                              void* d_out, int out_size)
{
    const float*    x     = (const float*)d_in[0];
    const uint32_t* qw    = (const uint32_t*)d_in[1];
    const float*    alpha = (const float*)d_in[2];
    const float*    qbias = (const float*)d_in[3];
    float*          out   = (float*)d_out;

    zero_out_kernel<<<(OUT_F + THREADS - 1) / THREADS, THREADS>>>(out);

    dim3 grid(NTILE, NCHUNK);
    lutgemm_kernel<<<grid, THREADS>>>(x, qw, alpha, qbias, out);
}

// round 4
// speedup vs baseline: 1.3498x; 1.3498x over previous
#include <cuda_runtime.h>
#include <stdint.h>

#define IN_F   4096
#define OUT_F  11008
#define BITS   4
#define GROUP  128

#define CHUNK    64                  // inputs per block (split-K chunk)
#define NCHUNK   (IN_F / CHUNK)      // 64
#define TILE_O   512                 // outputs per block (2 per thread)
#define NTILE    ((OUT_F + TILE_O - 1) / TILE_O)   // 22 (last block partial)
#define NTAB     (CHUNK / 8)         // 8 tables of 256 entries
#define THREADS  256

__global__ void __launch_bounds__(THREADS) zero_out_kernel(float* __restrict__ out) {
    int i = blockIdx.x * THREADS + threadIdx.x;
    if (i < OUT_F) out[i] = 0.0f;
}

__global__ void __launch_bounds__(THREADS) lutgemm_kernel(
    const float*    __restrict__ x,
    const uint32_t* __restrict__ qweight,
    const float*    __restrict__ alpha,
    const float*    __restrict__ qbias,
    float*          __restrict__ out)
{
    __shared__ float lut[NTAB * 256];      // 8 KB of sign-sum tables
    __shared__ float xs[CHUNK];
    __shared__ float ws[2];                // per-warp partials for chunk sum

    const int t     = threadIdx.x;
    const int chunk = blockIdx.y;                    // which 64-input slice
    const int o0    = blockIdx.x * TILE_O + 2 * t;   // this thread's 2 outputs

    // ---- stage x chunk + chunk sum (for the q_bias term) ----
    if (t < CHUNK) {
        float v = x[chunk * CHUNK + t];
        xs[t] = v;
        #pragma unroll
        for (int s = 16; s; s >>= 1) v += __shfl_down_sync(0xffffffffu, v, s);
        if ((t & 31) == 0) ws[t >> 5] = v;
    }
    __syncthreads();
    const float Sc = ws[0] + ws[1];   // sum of this chunk's x values

    // ---- build LUTs: each thread writes 8 gray-code-consecutive entries ----
    // Table tb covers inputs [chunk*64 + tb*8, +8); T[v] = sum_j (2*bit_j(v)-1)*x_j
    {
        const int tb = t >> 5;                 // 0..7
        const int s0 = (t & 31) * 8;           // run start (multiple of 8)
        const uint32_t g0 = (uint32_t)s0 ^ ((uint32_t)s0 >> 1);

        float x2[8];
        #pragma unroll
        for (int j = 0; j < 8; ++j) x2[j] = 2.0f * xs[tb * 8 + j];

        float acc = 0.0f;
        #pragma unroll
        for (int j = 0; j < 8; ++j)
            acc += ((g0 >> j) & 1u) ? 0.5f * x2[j] : -0.5f * x2[j];

        float* T = lut + tb * 256;
        T[g0] = acc;

        #pragma unroll
        for (int j = 1; j < 8; ++j) {
            const int k = (j & 1) ? 0 : (j & 2) ? 1 : 2;          // ctz(j), j<8
            const uint32_t g = g0 ^ (uint32_t)(j ^ (j >> 1));     // gray(s0+j)
            acc += ((g >> k) & 1u) ? x2[k] : -x2[k];
            T[g] = acc;
        }
    }
    __syncthreads();

    if (o0 >= OUT_F) return;   // only the last x-block has idle threads

    // ---- main lookup loop: 2 words x 4 bitplanes x 4 bytes x 2 outputs ----
    const int g = chunk >> 1;          // 128-input dequant group
    float2 p0 = {0.f, 0.f}, p1 = {0.f, 0.f}, p2 = {0.f, 0.f}, p3 = {0.f, 0.f};

    #pragma unroll
    for (int wl = 0; wl < 2; ++wl) {
        const int w = chunk * 2 + wl;
        const float* T = lut + wl * (4 * 256);
        const long base = (long)(w * BITS) * OUT_F + o0;

        const uint2 q0 = __ldg((const uint2*)(qweight + base));
        const uint2 q1 = __ldg((const uint2*)(qweight + base + OUT_F));
        const uint2 q2 = __ldg((const uint2*)(qweight + base + 2 * OUT_F));
        const uint2 q3 = __ldg((const uint2*)(qweight + base + 3 * OUT_F));

        p0.x += T[q0.x & 255u] + T[256 + ((q0.x >> 8) & 255u)]
              + T[512 + ((q0.x >> 16) & 255u)] + T[768 + (q0.x >> 24)];
        p0.y += T[q0.y & 255u] + T[256 + ((q0.y >> 8) & 255u)]
              + T[512 + ((q0.y >> 16) & 255u)] + T[768 + (q0.y >> 24)];

        p1.x += T[q1.x & 255u] + T[256 + ((q1.x >> 8) & 255u)]
              + T[512 + ((q1.x >> 16) & 255u)] + T[768 + (q1.x >> 24)];
        p1.y += T[q1.y & 255u] + T[256 + ((q1.y >> 8) & 255u)]
              + T[512 + ((q1.y >> 16) & 255u)] + T[768 + (q1.y >> 24)];

        p2.x += T[q2.x & 255u] + T[256 + ((q2.x >> 8) & 255u)]
              + T[512 + ((q2.x >> 16) & 255u)] + T[768 + (q2.x >> 24)];
        p2.y += T[q2.y & 255u] + T[256 + ((q2.y >> 8) & 255u)]
              + T[512 + ((q2.y >> 16) & 255u)] + T[768 + (q2.y >> 24)];

        p3.x += T[q3.x & 255u] + T[256 + ((q3.x >> 8) & 255u)]
              + T[512 + ((q3.x >> 16) & 255u)] + T[768 + (q3.x >> 24)];
        p3.y += T[q3.y & 255u] + T[256 + ((q3.y >> 8) & 255u)]
              + T[512 + ((q3.y >> 16) & 255u)] + T[768 + (q3.y >> 24)];
    }

    // ---- epilogue: alpha, q_bias, atomic accumulate ----
    const long ab = (long)(g * BITS) * OUT_F + o0;
    const float2 a0 = __ldg((const float2*)(alpha + ab));
    const float2 a1 = __ldg((const float2*)(alpha + ab + OUT_F));
    const float2 a2 = __ldg((const float2*)(alpha + ab + 2 * OUT_F));
    const float2 a3 = __ldg((const float2*)(alpha + ab + 3 * OUT_F));
    const float2 qb = __ldg((const float2*)(qbias + (long)g * OUT_F + o0));

    float yx = p0.x * a0.x + p1.x * a1.x + p2.x * a2.x + p3.x * a3.x + Sc * qb.x;
    float yy = p0.y * a0.y + p1.y * a1.y + p2.y * a2.y + p3.y * a3.y + Sc * qb.y;

    atomicAdd(out + o0,     yx);
    atomicAdd(out + o0 + 1, yy);
}

extern "C" void kernel_launch(void* const* d_in, const int* in_sizes, int n_in,
                              void* d_out, int out_size)
{
    const float*    x     = (const float*)d_in[0];
    const uint32_t* qw    = (const uint32_t*)d_in[1];
    const float*    alpha = (const float*)d_in[2];
    const float*    qbias = (const float*)d_in[3];
    float*          out   = (float*)d_out;

    zero_out_kernel<<<(OUT_F + THREADS - 1) / THREADS, THREADS>>>(out);

    dim3 grid(NTILE, NCHUNK);
    lutgemm_kernel<<<grid, THREADS>>>(x, qw, alpha, qbias, out);
}

// round 5
// speedup vs baseline: 1.3958x; 1.0341x over previous
#include <cuda_runtime.h>
#include <stdint.h>

#define IN_F   4096
#define OUT_F  11008
#define BITS   4
#define GROUP  128

#define CHUNK    64                  // inputs per block (split-K chunk)
#define NCHUNK   (IN_F / CHUNK)      // 64
#define OPT      4                   // outputs per thread
#define THREADS  256
#define TILE_O   (THREADS * OPT)     // 1024
#define NTILE    ((OUT_F + TILE_O - 1) / TILE_O)   // 11 (last block partial)
#define NTAB     (CHUNK / 8)         // 8 tables of 256 entries

__global__ void __launch_bounds__(THREADS, 5) lutgemm_kernel(
    const float*    __restrict__ x,
    const uint32_t* __restrict__ qweight,
    const float*    __restrict__ alpha,
    const float*    __restrict__ qbias,
    float*          __restrict__ out)
{
    __shared__ float lut[NTAB * 256];      // 8 KB of sign-sum tables
    __shared__ float xs[CHUNK];
    __shared__ float ws[2];

    const int t     = threadIdx.x;
    const int chunk = blockIdx.y;                      // which 64-input slice
    const int o0    = blockIdx.x * TILE_O + OPT * t;   // this thread's 4 outputs

    // ---- stage x chunk + chunk sum (for the q_bias term) ----
    if (t < CHUNK) {
        float v = x[chunk * CHUNK + t];
        xs[t] = v;
        #pragma unroll
        for (int s = 16; s; s >>= 1) v += __shfl_down_sync(0xffffffffu, v, s);
        if ((t & 31) == 0) ws[t >> 5] = v;
    }
    __syncthreads();
    const float Sc = ws[0] + ws[1];

    // ---- build LUTs: each thread writes 8 gray-code-consecutive entries ----
    {
        const int tb = t >> 5;                 // 0..7
        const int s0 = (t & 31) * 8;
        const uint32_t g0 = (uint32_t)s0 ^ ((uint32_t)s0 >> 1);

        float x2[8];
        #pragma unroll
        for (int j = 0; j < 8; ++j) x2[j] = 2.0f * xs[tb * 8 + j];

        float acc = 0.0f;
        #pragma unroll
        for (int j = 0; j < 8; ++j)
            acc += ((g0 >> j) & 1u) ? 0.5f * x2[j] : -0.5f * x2[j];

        float* T = lut + tb * 256;
        T[g0] = acc;

        #pragma unroll
        for (int j = 1; j < 8; ++j) {
            const int k = (j & 1) ? 0 : (j & 2) ? 1 : 2;          // ctz(j), j<8
            const uint32_t g = g0 ^ (uint32_t)(j ^ (j >> 1));     // gray(s0+j)
            acc += ((g >> k) & 1u) ? x2[k] : -x2[k];
            T[g] = acc;
        }
    }
    __syncthreads();

    if (o0 >= OUT_F) return;   // last x-block only; 768 tail is OPT-aligned

    // ---- main lookup loop: 2 words x 4 bitplanes x 4 outputs x 4 bytes ----
    const int g = chunk >> 1;          // 128-input dequant group
    float p[BITS][OPT];
    #pragma unroll
    for (int b = 0; b < BITS; ++b)
        #pragma unroll
        for (int c = 0; c < OPT; ++c) p[b][c] = 0.0f;

    #pragma unroll
    for (int wl = 0; wl < 2; ++wl) {
        const int w = chunk * 2 + wl;
        const char* Tb = (const char*)(lut + wl * (4 * 256));
        const long base = (long)(w * BITS) * OUT_F + o0;

        uint4 q[BITS];
        #pragma unroll
        for (int b = 0; b < BITS; ++b)
            q[b] = __ldg((const uint4*)(qweight + base + (long)b * OUT_F));

        #pragma unroll
        for (int b = 0; b < BITS; ++b) {
            const uint32_t qc[OPT] = {q[b].x, q[b].y, q[b].z, q[b].w};
            #pragma unroll
            for (int c = 0; c < OPT; ++c) {
                const uint32_t v = qc[c];
                p[b][c] += *(const float*)(Tb        + ((v <<  2) & 0x3FCu))
                         + *(const float*)(Tb + 1024 + ((v >>  6) & 0x3FCu))
                         + *(const float*)(Tb + 2048 + ((v >> 14) & 0x3FCu))
                         + *(const float*)(Tb + 3072 + ((v >> 22) & 0x3FCu));
            }
        }
    }

    // ---- epilogue: alpha, q_bias, atomic accumulate ----
    const long ab = (long)(g * BITS) * OUT_F + o0;
    const float4 a0 = __ldg((const float4*)(alpha + ab));
    const float4 a1 = __ldg((const float4*)(alpha + ab + OUT_F));
    const float4 a2 = __ldg((const float4*)(alpha + ab + 2 * OUT_F));
    const float4 a3 = __ldg((const float4*)(alpha + ab + 3 * OUT_F));
    const float4 qb = __ldg((const float4*)(qbias + (long)g * OUT_F + o0));

    const float ax[BITS][OPT] = {
        {a0.x, a0.y, a0.z, a0.w},
        {a1.x, a1.y, a1.z, a1.w},
        {a2.x, a2.y, a2.z, a2.w},
        {a3.x, a3.y, a3.z, a3.w}};
    const float qbv[OPT] = {qb.x, qb.y, qb.z, qb.w};

    #pragma unroll
    for (int c = 0; c < OPT; ++c) {
        float y = Sc * qbv[c];
        #pragma unroll
        for (int b = 0; b < BITS; ++b) y += p[b][c] * ax[b][c];
        atomicAdd(out + o0 + c, y);
    }
}

extern "C" void kernel_launch(void* const* d_in, const int* in_sizes, int n_in,
                              void* d_out, int out_size)
{
    const float*    x     = (const float*)d_in[0];
    const uint32_t* qw    = (const uint32_t*)d_in[1];
    const float*    alpha = (const float*)d_in[2];
    const float*    qbias = (const float*)d_in[3];
    float*          out   = (float*)d_out;

    cudaMemsetAsync(out, 0, OUT_F * sizeof(float));

    dim3 grid(NTILE, NCHUNK);
    lutgemm_kernel<<<grid, THREADS>>>(x, qw, alpha, qbias, out);
}

// round 6
// speedup vs baseline: 1.3985x; 1.0019x over previous
#include <cuda_runtime.h>
#include <stdint.h>

#define IN_F   4096
#define OUT_F  11008
#define BITS   4
#define GROUP  128

#define CHUNK    64                  // inputs per block (split-K chunk)
#define NCHUNK   (IN_F / CHUNK)      // 64
#define OPT      2                   // outputs per thread
#define THREADS  512
#define TILE_O   (THREADS * OPT)     // 1024
#define NTILE    ((OUT_F + TILE_O - 1) / TILE_O)   // 11 (last block partial)
#define NTAB     (CHUNK / 8)         // 8 tables of 256 entries

__global__ void __launch_bounds__(THREADS, 4) lutgemm_kernel(
    const float*    __restrict__ x,
    const uint32_t* __restrict__ qweight,
    const float*    __restrict__ alpha,
    const float*    __restrict__ qbias,
    float*          __restrict__ out)
{
    __shared__ float lut[NTAB * 256];      // 8 KB of sign-sum tables
    __shared__ float xs[CHUNK];
    __shared__ float ws[2];

    const int t     = threadIdx.x;
    const int chunk = blockIdx.y;                    // which 64-input slice
    const int o0    = blockIdx.x * TILE_O + 2 * t;   // this thread's 2 outputs

    // ---- stage x chunk + chunk sum (for the q_bias term) ----
    if (t < CHUNK) {
        float v = x[chunk * CHUNK + t];
        xs[t] = v;
        #pragma unroll
        for (int s = 16; s; s >>= 1) v += __shfl_down_sync(0xffffffffu, v, s);
        if ((t & 31) == 0) ws[t >> 5] = v;
    }
    __syncthreads();
    const float Sc = ws[0] + ws[1];

    // ---- build LUTs: 512 threads x 4 gray-code-consecutive entries ----
    // Table tb covers inputs [chunk*64 + tb*8, +8); T[v] = sum_j (2*bit_j(v)-1)*x_j
    {
        const int tb = t >> 6;                 // 0..7
        const int s0 = (t & 63) * 4;           // run start (multiple of 4)
        const uint32_t g0 = (uint32_t)s0 ^ ((uint32_t)s0 >> 1);

        float x2[8];
        #pragma unroll
        for (int j = 0; j < 8; ++j) x2[j] = 2.0f * xs[tb * 8 + j];

        float acc = 0.0f;
        #pragma unroll
        for (int j = 0; j < 8; ++j)
            acc += ((g0 >> j) & 1u) ? 0.5f * x2[j] : -0.5f * x2[j];

        float* T = lut + tb * 256;
        T[g0] = acc;

        #pragma unroll
        for (int j = 1; j < 4; ++j) {
            const int k = (j & 1) ? 0 : 1;                        // ctz(j), j<4
            const uint32_t g = g0 ^ (uint32_t)(j ^ (j >> 1));     // gray(s0+j)
            acc += ((g >> k) & 1u) ? x2[k] : -x2[k];
            T[g] = acc;
        }
    }
    __syncthreads();

    if (o0 >= OUT_F) return;   // only last x-tile has idle threads

    // ---- main lookup loop: 2 words x 4 bitplanes x 2 outputs x 4 bytes ----
    const int g = chunk >> 1;          // 128-input dequant group
    float2 p0 = {0.f, 0.f}, p1 = {0.f, 0.f}, p2 = {0.f, 0.f}, p3 = {0.f, 0.f};

    #pragma unroll
    for (int wl = 0; wl < 2; ++wl) {
        const int w = chunk * 2 + wl;
        const char* Tb = (const char*)(lut + wl * (4 * 256));
        const long base = (long)(w * BITS) * OUT_F + o0;

        const uint2 q0 = __ldg((const uint2*)(qweight + base));
        const uint2 q1 = __ldg((const uint2*)(qweight + base + OUT_F));
        const uint2 q2 = __ldg((const uint2*)(qweight + base + 2 * OUT_F));
        const uint2 q3 = __ldg((const uint2*)(qweight + base + 3 * OUT_F));

        #define LKP(dst, v)                                                     \
            dst += *(const float*)(Tb        + (((v) <<  2) & 0x3FCu))          \
                 + *(const float*)(Tb + 1024 + (((v) >>  6) & 0x3FCu))          \
                 + *(const float*)(Tb + 2048 + (((v) >> 14) & 0x3FCu))          \
                 + *(const float*)(Tb + 3072 + (((v) >> 22) & 0x3FCu))

        LKP(p0.x, q0.x); LKP(p0.y, q0.y);
        LKP(p1.x, q1.x); LKP(p1.y, q1.y);
        LKP(p2.x, q2.x); LKP(p2.y, q2.y);
        LKP(p3.x, q3.x); LKP(p3.y, q3.y);
        #undef LKP
    }

    // ---- epilogue: alpha, q_bias, atomic accumulate ----
    const long ab = (long)(g * BITS) * OUT_F + o0;
    const float2 a0 = __ldg((const float2*)(alpha + ab));
    const float2 a1 = __ldg((const float2*)(alpha + ab + OUT_F));
    const float2 a2 = __ldg((const float2*)(alpha + ab + 2 * OUT_F));
    const float2 a3 = __ldg((const float2*)(alpha + ab + 3 * OUT_F));
    const float2 qb = __ldg((const float2*)(qbias + (long)g * OUT_F + o0));

    float yx = p0.x * a0.x + p1.x * a1.x + p2.x * a2.x + p3.x * a3.x + Sc * qb.x;
    float yy = p0.y * a0.y + p1.y * a1.y + p2.y * a2.y + p3.y * a3.y + Sc * qb.y;

    atomicAdd(out + o0,     yx);
    atomicAdd(out + o0 + 1, yy);
}

extern "C" void kernel_launch(void* const* d_in, const int* in_sizes, int n_in,
                              void* d_out, int out_size)
{
    const float*    x     = (const float*)d_in[0];
    const uint32_t* qw    = (const uint32_t*)d_in[1];
    const float*    alpha = (const float*)d_in[2];
    const float*    qbias = (const float*)d_in[3];
    float*          out   = (float*)d_out;

    cudaMemsetAsync(out, 0, OUT_F * sizeof(float));

    dim3 grid(NTILE, NCHUNK);
    lutgemm_kernel<<<grid, THREADS>>>(x, qw, alpha, qbias, out);
}